// round 2
// baseline (speedup 1.0000x reference)
#include <cuda_runtime.h>
#include <math.h>

#define BATCH 32
#define LDIM  4096
#define MEMD  256
#define QDIM  256
#define TILE  64
#define NCHUNK (LDIM / TILE)   // 64
#define NTURN 5

// ---------------- device scratch (no mallocs allowed) ----------------
__device__ float g_s[BATCH * QDIM];
__device__ float g_qb[BATCH * MEMD];
__device__ float g_qa[BATCH * MEMD];
__device__ float g_qe[BATCH * MEMD];
__device__ float g_endvec[BATCH * MEMD];
__device__ float g_x1[BATCH * MEMD];
__device__ float g_scores_start[BATCH * LDIM];
__device__ float g_scores_end[BATCH * LDIM];
__device__ float g_partV1[BATCH * NCHUNK * MEMD];
__device__ float g_partV2[BATCH * NCHUNK * MEMD];
__device__ float g_partM1[BATCH * NCHUNK];
__device__ float g_partZ1[BATCH * NCHUNK];
__device__ float g_partM2[BATCH * NCHUNK];
__device__ float g_partZ2[BATCH * NCHUNK];

// ---------------- helpers ----------------
__device__ __forceinline__ void cp16(void* smem, const void* g) {
    unsigned a = (unsigned)__cvta_generic_to_shared(smem);
    asm volatile("cp.async.cg.shared.global [%0], [%1], 16;\n" :: "r"(a), "l"(g));
}
__device__ __forceinline__ void cp_commit_wait() {
    asm volatile("cp.async.commit_group;\n");
    asm volatile("cp.async.wait_group 0;\n");
}
__device__ __forceinline__ float dot44(const float4 a, const float4 x) {
    return a.x * x.x + a.y * x.y + a.z * x.z + a.w * x.w;
}

// ---------------- init: zero output accumulators, copy s0 ----------------
__global__ void k_init(float* __restrict__ out, const float* __restrict__ s0, int outn) {
    int i = blockIdx.x * 256 + threadIdx.x;
    if (i < outn) out[i] = 0.0f;
    if (i < BATCH * QDIM) g_s[i] = s0[i];
}

// ---------------- dual vec-mat: qb = X@Wb^T, qa = X@Wa^T ----------------
// grid (4, 2), 256 threads. If X==nullptr uses g_s.
__global__ void k_vm2(const float* __restrict__ X,
                      const float* __restrict__ Wb,
                      const float* __restrict__ Wa) {
    __shared__ float xs[BATCH * 257];
    const float* Xp = X ? X : g_s;
    int t = threadIdx.x;
    for (int i = t; i < BATCH * QDIM; i += 256)
        xs[(i >> 8) * 257 + (i & 255)] = Xp[i];
    __syncthreads();
    const float* W = blockIdx.y ? Wa : Wb;
    float* outv = blockIdx.y ? g_qa : g_qb;
    int w = t >> 5, lane = t & 31;
    int nbase = blockIdx.x * 64 + w * 8;
    const float* xrow = &xs[lane * 257];
    for (int r = 0; r < 8; r++) {
        int n = nbase + r;
        const float4* Wr = (const float4*)(W + n * 256);
        float acc = 0.0f;
        #pragma unroll 8
        for (int k4 = 0; k4 < 64; k4++) {
            float4 wv = __ldg(Wr + k4);
            int k = k4 * 4;
            acc += wv.x * xrow[k] + wv.y * xrow[k + 1] + wv.z * xrow[k + 2] + wv.w * xrow[k + 3];
        }
        outv[lane * MEMD + n] = acc;
    }
}

// ---------------- big fused pass over M ----------------
// grid (NCHUNK, BATCH), 256 threads.
// doMain: compute start/alpha scores + softmax-weighted partials for end_vec/x1
// doEnd:  compute end scores (dot with g_qe) and store them
__global__ void __launch_bounds__(256, 2)
k_bigpass(const float* __restrict__ M, int doMain, int doEnd) {
    extern __shared__ float sm[];
    float* tile = sm;                         // TILE*MEMD = 16384
    float* cV1 = sm + TILE * MEMD;            // 8*256
    float* cV2 = cV1 + 8 * MEMD;              // 8*256
    float* cm1 = cV2 + 8 * MEMD;              // 8
    float* cz1 = cm1 + 8;
    float* cm2 = cz1 + 8;
    float* cz2 = cm2 + 8;

    int b = blockIdx.y, chunk = blockIdx.x;
    int t = threadIdx.x, w = t >> 5, k = t & 31;
    const float* Mb = M + ((size_t)b * LDIM + (size_t)chunk * TILE) * MEMD;

    #pragma unroll
    for (int i = 0; i < 16; i++) {
        int e4 = i * 256 + t;                 // float4 index within 64KB tile
        cp16(tile + e4 * 4, Mb + e4 * 4);
    }
    cp_commit_wait();
    __syncthreads();

    float4 qb0 = make_float4(0,0,0,0), qb1 = qb0, qa0 = qb0, qa1 = qb0, qe0 = qb0, qe1 = qb0;
    const int bo = b * MEMD + 4 * k;
    if (doMain) {
        qb0 = *(const float4*)(g_qb + bo);
        qb1 = *(const float4*)(g_qb + bo + 128);
        qa0 = *(const float4*)(g_qa + bo);
        qa1 = *(const float4*)(g_qa + bo + 128);
    }
    if (doEnd) {
        qe0 = *(const float4*)(g_qe + bo);
        qe1 = *(const float4*)(g_qe + bo + 128);
    }

    const float4* tf = (const float4*)tile;
    int rowbase = w * 8;
    int lbase = b * LDIM + chunk * TILE + rowbase;

    float sb[8], sa[8];
    #pragma unroll
    for (int r = 0; r < 8; r++) {
        float4 x0 = tf[(rowbase + r) * 64 + k];
        float4 x1 = tf[(rowbase + r) * 64 + 32 + k];
        float db = 0.0f, da = 0.0f, de = 0.0f;
        if (doMain) {
            db = dot44(qb0, x0) + dot44(qb1, x1);
            da = dot44(qa0, x0) + dot44(qa1, x1);
        }
        if (doEnd) de = dot44(qe0, x0) + dot44(qe1, x1);
        #pragma unroll
        for (int off = 16; off > 0; off >>= 1) {
            db += __shfl_xor_sync(0xffffffffu, db, off);
            da += __shfl_xor_sync(0xffffffffu, da, off);
            de += __shfl_xor_sync(0xffffffffu, de, off);
        }
        sb[r] = db; sa[r] = da;
        if (k == 0) {
            if (doMain) g_scores_start[lbase + r] = db;
            if (doEnd)  g_scores_end[lbase + r] = de;
        }
    }

    if (doMain) {
        float m1 = -1e30f, m2 = -1e30f;
        #pragma unroll
        for (int r = 0; r < 8; r++) { m1 = fmaxf(m1, sb[r]); m2 = fmaxf(m2, sa[r]); }
        float w1[8], w2[8];
        float Z1 = 0.0f, Z2 = 0.0f;
        #pragma unroll
        for (int r = 0; r < 8; r++) {
            w1[r] = __expf(sb[r] - m1); Z1 += w1[r];
            w2[r] = __expf(sa[r] - m2); Z2 += w2[r];
        }
        float4 V10 = make_float4(0,0,0,0), V11 = V10, V20 = V10, V21 = V10;
        #pragma unroll
        for (int r = 0; r < 8; r++) {
            float4 x0 = tf[(rowbase + r) * 64 + k];
            float4 x1 = tf[(rowbase + r) * 64 + 32 + k];
            V10.x += w1[r] * x0.x; V10.y += w1[r] * x0.y; V10.z += w1[r] * x0.z; V10.w += w1[r] * x0.w;
            V11.x += w1[r] * x1.x; V11.y += w1[r] * x1.y; V11.z += w1[r] * x1.z; V11.w += w1[r] * x1.w;
            V20.x += w2[r] * x0.x; V20.y += w2[r] * x0.y; V20.z += w2[r] * x0.z; V20.w += w2[r] * x0.w;
            V21.x += w2[r] * x1.x; V21.y += w2[r] * x1.y; V21.z += w2[r] * x1.z; V21.w += w2[r] * x1.w;
        }
        *(float4*)(cV1 + w * MEMD + 4 * k) = V10;
        *(float4*)(cV1 + w * MEMD + 128 + 4 * k) = V11;
        *(float4*)(cV2 + w * MEMD + 4 * k) = V20;
        *(float4*)(cV2 + w * MEMD + 128 + 4 * k) = V21;
        if (k == 0) { cm1[w] = m1; cz1[w] = Z1; cm2[w] = m2; cz2[w] = Z2; }
        __syncthreads();

        int j = t;
        float mg1 = cm1[0], mg2 = cm2[0];
        #pragma unroll
        for (int wi = 1; wi < 8; wi++) { mg1 = fmaxf(mg1, cm1[wi]); mg2 = fmaxf(mg2, cm2[wi]); }
        float vg1 = 0.0f, zg1 = 0.0f, vg2 = 0.0f, zg2 = 0.0f;
        #pragma unroll
        for (int wi = 0; wi < 8; wi++) {
            float s1 = __expf(cm1[wi] - mg1);
            float s2 = __expf(cm2[wi] - mg2);
            vg1 += s1 * cV1[wi * MEMD + j];
            zg1 += s1 * cz1[wi];
            vg2 += s2 * cV2[wi * MEMD + j];
            zg2 += s2 * cz2[wi];
        }
        int pidx = b * NCHUNK + chunk;
        g_partV1[pidx * MEMD + j] = vg1;
        g_partV2[pidx * MEMD + j] = vg2;
        if (t == 0) {
            g_partM1[pidx] = mg1; g_partZ1[pidx] = zg1;
            g_partM2[pidx] = mg2; g_partZ2[pidx] = zg2;
        }
    }
}

// ---------------- softmax over stored scores, accumulate probs into out ----------------
// grid (BATCH, 2): y=0 start half, y=1 end half
__global__ void k_softmax_acc(float* __restrict__ out, int doStart, int doEnd) {
    int which = blockIdx.y;
    if (which == 0 ? !doStart : !doEnd) return;
    int b = blockIdx.x, t = threadIdx.x;
    const float* sc = (which ? g_scores_end : g_scores_start) + b * LDIM;
    float* o = out + (size_t)which * BATCH * LDIM + b * LDIM;

    float v[16];
    float lm = -1e30f;
    #pragma unroll
    for (int i = 0; i < 16; i++) { v[i] = sc[i * 256 + t]; lm = fmaxf(lm, v[i]); }

    __shared__ float red[8];
    __shared__ float bc[2];
    #pragma unroll
    for (int off = 16; off > 0; off >>= 1) lm = fmaxf(lm, __shfl_xor_sync(0xffffffffu, lm, off));
    if ((t & 31) == 0) red[t >> 5] = lm;
    __syncthreads();
    if (t == 0) {
        float m = red[0];
        for (int i = 1; i < 8; i++) m = fmaxf(m, red[i]);
        bc[0] = m;
    }
    __syncthreads();
    float m = bc[0];

    float ls = 0.0f;
    #pragma unroll
    for (int i = 0; i < 16; i++) { v[i] = __expf(v[i] - m); ls += v[i]; }
    #pragma unroll
    for (int off = 16; off > 0; off >>= 1) ls += __shfl_xor_sync(0xffffffffu, ls, off);
    __syncthreads();
    if ((t & 31) == 0) red[t >> 5] = ls;
    __syncthreads();
    if (t == 0) {
        float z = 0.0f;
        for (int i = 0; i < 8; i++) z += red[i];
        bc[1] = 1.0f / z;
    }
    __syncthreads();
    float invz = bc[1];
    #pragma unroll
    for (int i = 0; i < 16; i++) o[i * 256 + t] += v[i] * invz;
}

// ---------------- merge per-chunk softmax partials -> end_vec, x1 ----------------
// grid (BATCH), 256 threads (thread = column j)
__global__ void k_reduce() {
    int b = blockIdx.x, j = threadIdx.x;
    float mg1 = -1e30f, mg2 = -1e30f;
    #pragma unroll 8
    for (int c = 0; c < NCHUNK; c++) {
        mg1 = fmaxf(mg1, g_partM1[b * NCHUNK + c]);
        mg2 = fmaxf(mg2, g_partM2[b * NCHUNK + c]);
    }
    float v1 = 0.0f, z1 = 0.0f, v2 = 0.0f, z2 = 0.0f;
    #pragma unroll 4
    for (int c = 0; c < NCHUNK; c++) {
        int p = b * NCHUNK + c;
        float s1 = __expf(g_partM1[p] - mg1);
        float s2 = __expf(g_partM2[p] - mg2);
        v1 += s1 * g_partV1[p * MEMD + j];
        z1 += s1 * g_partZ1[p];
        v2 += s2 * g_partV2[p * MEMD + j];
        z2 += s2 * g_partZ2[p];
    }
    g_endvec[b * MEMD + j] = v1 / z1;
    g_x1[b * MEMD + j] = v2 / z2;
}

// ---------------- per-turn tail: qe = [s|end_vec]@We^T, GRU step -> new s ----------------
// grid (8) column-slice CTAs of 256 threads, lane = batch
__global__ void k_turn2(const float* __restrict__ We,
                        const float* __restrict__ W_ih,
                        const float* __restrict__ W_hh,
                        const float* __restrict__ b_ih,
                        const float* __restrict__ b_hh) {
    extern __shared__ float sm[];
    float* ss  = sm;                    // 32*257
    float* ev  = ss + 32 * 257;
    float* xx  = ev + 32 * 257;
    float* qeo = xx + 32 * 257;         // 32*33
    float* gio = qeo + 32 * 33;         // 96*33
    float* gho = gio + 96 * 33;         // 96*33

    int c = blockIdx.x, t = threadIdx.x;
    for (int i = t; i < BATCH * MEMD; i += 256) {
        int bb = i >> 8, kk = i & 255;
        ss[bb * 257 + kk] = g_s[i];
        ev[bb * 257 + kk] = g_endvec[i];
        xx[bb * 257 + kk] = g_x1[i];
    }
    __syncthreads();

    int w = t >> 5, lane = t & 31;
    const float* srow = &ss[lane * 257];
    const float* erow = &ev[lane * 257];
    const float* xrow = &xx[lane * 257];

    for (int R = w; R < 224; R += 8) {
        float acc;
        if (R < 32) {
            int n = c * 32 + R;
            const float4* Wr0 = (const float4*)(We + (size_t)n * 512);
            const float4* Wr1 = (const float4*)(We + (size_t)n * 512 + 256);
            acc = 0.0f;
            #pragma unroll 8
            for (int k4 = 0; k4 < 64; k4++) {
                float4 wv = __ldg(Wr0 + k4);
                int k = k4 * 4;
                acc += wv.x * srow[k] + wv.y * srow[k + 1] + wv.z * srow[k + 2] + wv.w * srow[k + 3];
            }
            #pragma unroll 8
            for (int k4 = 0; k4 < 64; k4++) {
                float4 wv = __ldg(Wr1 + k4);
                int k = k4 * 4;
                acc += wv.x * erow[k] + wv.y * erow[k + 1] + wv.z * erow[k + 2] + wv.w * erow[k + 3];
            }
            qeo[R * 33 + lane] = acc;
        } else if (R < 128) {
            int idx = R - 32;
            int g = (idx >> 5) * 256 + c * 32 + (idx & 31);
            const float4* Wr = (const float4*)(W_ih + (size_t)g * 256);
            acc = __ldg(b_ih + g);
            #pragma unroll 8
            for (int k4 = 0; k4 < 64; k4++) {
                float4 wv = __ldg(Wr + k4);
                int k = k4 * 4;
                acc += wv.x * xrow[k] + wv.y * xrow[k + 1] + wv.z * xrow[k + 2] + wv.w * xrow[k + 3];
            }
            gio[idx * 33 + lane] = acc;
        } else {
            int idx = R - 128;
            int g = (idx >> 5) * 256 + c * 32 + (idx & 31);
            const float4* Wr = (const float4*)(W_hh + (size_t)g * 256);
            acc = __ldg(b_hh + g);
            #pragma unroll 8
            for (int k4 = 0; k4 < 64; k4++) {
                float4 wv = __ldg(Wr + k4);
                int k = k4 * 4;
                acc += wv.x * srow[k] + wv.y * srow[k + 1] + wv.z * srow[k + 2] + wv.w * srow[k + 3];
            }
            gho[idx * 33 + lane] = acc;
        }
    }
    __syncthreads();

    for (int p = t; p < 1024; p += 256) {
        int bb = p >> 5, jl = p & 31;
        float gir = gio[jl * 33 + bb], giz = gio[(32 + jl) * 33 + bb], gin = gio[(64 + jl) * 33 + bb];
        float ghr = gho[jl * 33 + bb], ghz = gho[(32 + jl) * 33 + bb], ghn = gho[(64 + jl) * 33 + bb];
        float r = 1.0f / (1.0f + __expf(-(gir + ghr)));
        float z = 1.0f / (1.0f + __expf(-(giz + ghz)));
        float n = tanhf(gin + r * ghn);
        int col = c * 32 + jl;
        float sold = ss[bb * 257 + col];
        g_s[bb * MEMD + col] = (1.0f - z) * n + z * sold;
        g_qe[bb * MEMD + col] = qeo[jl * 33 + bb];
    }
}

// ---------------- finalize: out = log(acc / NTURN) ----------------
__global__ void k_final(float* __restrict__ out, int n) {
    int i = blockIdx.x * 256 + threadIdx.x;
    if (i < n) out[i] = logf(out[i] * (1.0f / NTURN));
}

// ---------------- launch ----------------
extern "C" void kernel_launch(void* const* d_in, const int* in_sizes, int n_in,
                              void* d_out, int out_size) {
    (void)in_sizes; (void)n_in;
    const float* M    = (const float*)d_in[0];
    const float* s0   = (const float*)d_in[1];
    const float* Wb   = (const float*)d_in[2];
    const float* We   = (const float*)d_in[3];
    const float* Wa   = (const float*)d_in[4];
    const float* W_ih = (const float*)d_in[5];
    const float* W_hh = (const float*)d_in[6];
    const float* b_ih = (const float*)d_in[7];
    const float* b_hh = (const float*)d_in[8];
    float* out = (float*)d_out;

    const int BIG_SMEM = (TILE * MEMD + 16 * MEMD + 32) * 4;          // 82,048 B
    const int T2_SMEM  = (3 * 32 * 257 + 32 * 33 + 2 * 96 * 33) * 4;  // 128,256 B
    cudaFuncSetAttribute(k_bigpass, cudaFuncAttributeMaxDynamicSharedMemorySize, BIG_SMEM);
    cudaFuncSetAttribute(k_turn2,   cudaFuncAttributeMaxDynamicSharedMemorySize, T2_SMEM);

    int gblocks = (out_size + 255) / 256;
    if (gblocks < 32) gblocks = 32;
    k_init<<<gblocks, 256>>>(out, s0, out_size);
    k_vm2<<<dim3(4, 2), 256>>>(s0, Wb, Wa);

    for (int tn = 0; tn < NTURN; tn++) {
        k_bigpass<<<dim3(NCHUNK, BATCH), 256, BIG_SMEM>>>(M, 1, tn > 0 ? 1 : 0);
        k_softmax_acc<<<dim3(BATCH, 2), 256>>>(out, 1, tn > 0 ? 1 : 0);
        k_reduce<<<BATCH, 256>>>();
        k_turn2<<<8, 256, T2_SMEM>>>(We, W_ih, W_hh, b_ih, b_hh);
        k_vm2<<<dim3(4, 2), 256>>>(nullptr, Wb, Wa);
    }
    // final end-scores pass with qe(4)
    k_bigpass<<<dim3(NCHUNK, BATCH), 256, BIG_SMEM>>>(M, 0, 1);
    k_softmax_acc<<<dim3(BATCH, 2), 256>>>(out, 0, 1);
    k_final<<<(out_size + 255) / 256, 256>>>(out, out_size);
}

// round 3
// speedup vs baseline: 1.0633x; 1.0633x over previous
#include <cuda_runtime.h>
#include <math.h>

#define BATCH 32
#define LDIM  4096
#define MEMD  256
#define NTURN 5
#define CPB   9                     // CTAs per batch in k_big
#define G_CTAS (BATCH * CPB)        // 288
#define NSUB  (LDIM / 32)           // 128 subtiles of 32 rows per batch
#define BIG_SMEM ((8192 * 2 + 2048 * 2) * 4)   // 81920 B

// ---------------- device scratch ----------------
__device__ float g_s[BATCH * MEMD];
__device__ float g_qb[BATCH * MEMD];
__device__ float g_qa[BATCH * MEMD];
__device__ float g_qe[BATCH * MEMD];
__device__ float g_endvec[BATCH * MEMD];
__device__ float g_x1[BATCH * MEMD];
__device__ float g_scoreS[BATCH * LDIM];
__device__ float g_scoreE[BATCH * LDIM];
__device__ float g_pV1[G_CTAS * MEMD];
__device__ float g_pV2[G_CTAS * MEMD];
__device__ float g_pm1[G_CTAS], g_pz1[G_CTAS], g_pm2[G_CTAS], g_pz2[G_CTAS];

// ---------------- helpers ----------------
__device__ __forceinline__ void cp16(void* smem, const void* g) {
    unsigned a = (unsigned)__cvta_generic_to_shared(smem);
    asm volatile("cp.async.cg.shared.global [%0], [%1], 16;\n" :: "r"(a), "l"(g));
}
__device__ __forceinline__ float dot44(float4 a, float4 x) {
    return a.x * x.x + a.y * x.y + a.z * x.z + a.w * x.w;
}
__device__ __forceinline__ void scale4(float4& v, float s) {
    v.x *= s; v.y *= s; v.z *= s; v.w *= s;
}
__device__ __forceinline__ void fma4(float4& v, float s, float4 x) {
    v.x += s * x.x; v.y += s * x.y; v.z += s * x.z; v.w += s * x.w;
}

// ---------------- init ----------------
__global__ void k_init(float* __restrict__ out, const float* __restrict__ s0, int outn) {
    int i = blockIdx.x * 256 + threadIdx.x;
    if (i < outn) out[i] = 0.0f;
    if (i < BATCH * MEMD) g_s[i] = s0[i];
}

// ---------------- dual vec-mat: qb = X@Wb^T, qa = X@Wa^T ----------------
__global__ void k_vm2(const float* __restrict__ X,
                      const float* __restrict__ Wb,
                      const float* __restrict__ Wa) {
    __shared__ float xs[BATCH * 257];
    const float* Xp = X ? X : g_s;
    int t = threadIdx.x;
    for (int i = t; i < BATCH * MEMD; i += 256)
        xs[(i >> 8) * 257 + (i & 255)] = Xp[i];
    __syncthreads();
    const float* W = blockIdx.y ? Wa : Wb;
    float* outv = blockIdx.y ? g_qa : g_qb;
    int w = t >> 5, lane = t & 31;
    int nbase = blockIdx.x * 64 + w * 8;
    const float* xrow = &xs[lane * 257];
    for (int r = 0; r < 8; r++) {
        int n = nbase + r;
        const float4* Wr = (const float4*)(W + n * 256);
        float acc = 0.0f;
        #pragma unroll 8
        for (int k4 = 0; k4 < 64; k4++) {
            float4 wv = __ldg(Wr + k4);
            int k = k4 * 4;
            acc += wv.x * xrow[k] + wv.y * xrow[k + 1] + wv.z * xrow[k + 2] + wv.w * xrow[k + 3];
        }
        outv[lane * MEMD + n] = acc;
    }
}

// ---------------- persistent big pass over M ----------------
// grid G_CTAS (9 CTAs per batch, all resident), 256 threads, 2 CTAs/SM.
// Double-buffered cp.async streaming of 32-row subtiles (32 KB each).
// doMain: start/alpha scores -> online softmax with register V accumulators.
// doEnd:  end scores written to g_scoreE (softmaxed later).
__global__ void __launch_bounds__(256, 2)
k_big(const float* __restrict__ M, int doMain, int doEnd) {
    extern __shared__ float sm[];
    float* bufA = sm;              // 8192 floats (32 KB)
    float* bufB = sm + 8192;
    float* cV1  = sm + 16384;      // 8*256
    float* cV2  = sm + 18432;      // 8*256
    __shared__ float cm1[8], cz1[8], cm2[8], cz2[8];

    const int b  = blockIdx.x / CPB;
    const int cb = blockIdx.x % CPB;
    const int s0 = (cb * NSUB) / CPB;
    const int s1 = ((cb + 1) * NSUB) / CPB;
    const int t = threadIdx.x, w = t >> 5, k = t & 31;

    // prefetch first subtile
    {
        const float* src = M + ((size_t)b * LDIM + (size_t)s0 * 32) * MEMD;
        #pragma unroll
        for (int j = 0; j < 8; j++) {
            int e4 = j * 256 + t;
            cp16(bufA + e4 * 4, src + (size_t)e4 * 4);
        }
        asm volatile("cp.async.commit_group;\n");
    }

    float4 z4 = make_float4(0.f, 0.f, 0.f, 0.f);
    float4 qb0 = z4, qb1 = z4, qa0 = z4, qa1 = z4, qe0 = z4, qe1 = z4;
    const int bo = b * MEMD + 4 * k;
    if (doMain) {
        qb0 = *(const float4*)(g_qb + bo); qb1 = *(const float4*)(g_qb + bo + 128);
        qa0 = *(const float4*)(g_qa + bo); qa1 = *(const float4*)(g_qa + bo + 128);
    }
    if (doEnd) {
        qe0 = *(const float4*)(g_qe + bo); qe1 = *(const float4*)(g_qe + bo + 128);
    }

    float m1 = -1e30f, z1 = 0.f, m2 = -1e30f, z2 = 0.f;
    float4 V10 = z4, V11 = z4, V20 = z4, V21 = z4;

    for (int g = s0; g < s1; ++g) {
        float* cbuf = ((g - s0) & 1) ? bufB : bufA;
        float* nbuf = ((g - s0) & 1) ? bufA : bufB;
        if (g + 1 < s1) {
            const float* src = M + ((size_t)b * LDIM + (size_t)(g + 1) * 32) * MEMD;
            #pragma unroll
            for (int j = 0; j < 8; j++) {
                int e4 = j * 256 + t;
                cp16(nbuf + e4 * 4, src + (size_t)e4 * 4);
            }
            asm volatile("cp.async.commit_group;\n");
            asm volatile("cp.async.wait_group 1;\n");
        } else {
            asm volatile("cp.async.wait_group 0;\n");
        }
        __syncthreads();

        const float4* tf = (const float4*)cbuf;
        const int lbase = b * LDIM + g * 32;

        #pragma unroll
        for (int i = 0; i < 4; i++) {
            int row = (w << 2) + i;
            float4 x0  = tf[row * 64 + k];
            float4 x1v = tf[row * 64 + 32 + k];
            float db = 0.f, da = 0.f, de = 0.f;
            if (doMain) {
                db = dot44(qb0, x0) + dot44(qb1, x1v);
                da = dot44(qa0, x0) + dot44(qa1, x1v);
            }
            if (doEnd) de = dot44(qe0, x0) + dot44(qe1, x1v);
            #pragma unroll
            for (int off = 16; off; off >>= 1) {
                db += __shfl_xor_sync(~0u, db, off);
                da += __shfl_xor_sync(~0u, da, off);
                de += __shfl_xor_sync(~0u, de, off);
            }
            if (doMain) {
                if (db > m1) {
                    float sc = __expf(m1 - db);
                    z1 *= sc; scale4(V10, sc); scale4(V11, sc); m1 = db;
                }
                float w1 = __expf(db - m1);
                z1 += w1; fma4(V10, w1, x0); fma4(V11, w1, x1v);
                if (da > m2) {
                    float sc = __expf(m2 - da);
                    z2 *= sc; scale4(V20, sc); scale4(V21, sc); m2 = da;
                }
                float w2 = __expf(da - m2);
                z2 += w2; fma4(V20, w2, x0); fma4(V21, w2, x1v);
            }
            if (k == 0) {
                if (doMain) g_scoreS[lbase + row] = db;
                if (doEnd)  g_scoreE[lbase + row] = de;
            }
        }
        __syncthreads();   // cbuf free for next prefetch
    }

    // single CTA-combine + partial write
    if (doMain) {
        *(float4*)(cV1 + w * MEMD + 4 * k)       = V10;
        *(float4*)(cV1 + w * MEMD + 128 + 4 * k) = V11;
        *(float4*)(cV2 + w * MEMD + 4 * k)       = V20;
        *(float4*)(cV2 + w * MEMD + 128 + 4 * k) = V21;
        if (k == 0) { cm1[w] = m1; cz1[w] = z1; cm2[w] = m2; cz2[w] = z2; }
        __syncthreads();
        float a1 = cm1[0], a2 = cm2[0];
        #pragma unroll
        for (int wi = 1; wi < 8; wi++) {
            a1 = fmaxf(a1, cm1[wi]); a2 = fmaxf(a2, cm2[wi]);
        }
        float v1 = 0.f, gz1 = 0.f, v2 = 0.f, gz2 = 0.f;
        #pragma unroll
        for (int wi = 0; wi < 8; wi++) {
            float e1 = __expf(cm1[wi] - a1), e2 = __expf(cm2[wi] - a2);
            v1 += e1 * cV1[wi * MEMD + t]; gz1 += e1 * cz1[wi];
            v2 += e2 * cV2[wi * MEMD + t]; gz2 += e2 * cz2[wi];
        }
        int slot = blockIdx.x;
        g_pV1[slot * MEMD + t] = v1;
        g_pV2[slot * MEMD + t] = v2;
        if (t == 0) {
            g_pm1[slot] = a1; g_pz1[slot] = gz1;
            g_pm2[slot] = a2; g_pz2[slot] = gz2;
        }
    }
}

// ---------------- softmax over stored scores, accumulate probs into out ----------------
__global__ void k_softmax_acc(float* __restrict__ out, int doStart, int doEnd) {
    int which = blockIdx.y;
    if (which == 0 ? !doStart : !doEnd) return;
    int b = blockIdx.x, t = threadIdx.x;
    const float* sc = (which ? g_scoreE : g_scoreS) + b * LDIM;
    float* o = out + (size_t)which * BATCH * LDIM + b * LDIM;

    float v[16];
    float lm = -1e30f;
    #pragma unroll
    for (int i = 0; i < 16; i++) { v[i] = sc[i * 256 + t]; lm = fmaxf(lm, v[i]); }

    __shared__ float red[8];
    __shared__ float bc[2];
    #pragma unroll
    for (int off = 16; off; off >>= 1) lm = fmaxf(lm, __shfl_xor_sync(~0u, lm, off));
    if ((t & 31) == 0) red[t >> 5] = lm;
    __syncthreads();
    if (t == 0) {
        float m = red[0];
        for (int i = 1; i < 8; i++) m = fmaxf(m, red[i]);
        bc[0] = m;
    }
    __syncthreads();
    float m = bc[0];
    float ls = 0.0f;
    #pragma unroll
    for (int i = 0; i < 16; i++) { v[i] = __expf(v[i] - m); ls += v[i]; }
    #pragma unroll
    for (int off = 16; off; off >>= 1) ls += __shfl_xor_sync(~0u, ls, off);
    __syncthreads();
    if ((t & 31) == 0) red[t >> 5] = ls;
    __syncthreads();
    if (t == 0) {
        float z = 0.0f;
        for (int i = 0; i < 8; i++) z += red[i];
        bc[1] = 1.0f / z;
    }
    __syncthreads();
    float invz = bc[1];
    #pragma unroll
    for (int i = 0; i < 16; i++) o[i * 256 + t] += v[i] * invz;
}

// ---------------- merge per-CTA partials -> end_vec, x1 ----------------
__global__ void k_reduce() {
    int b = blockIdx.x, j = threadIdx.x;
    int base = b * CPB;
    float mg1 = -1e30f, mg2 = -1e30f;
    #pragma unroll
    for (int c = 0; c < CPB; c++) {
        mg1 = fmaxf(mg1, g_pm1[base + c]);
        mg2 = fmaxf(mg2, g_pm2[base + c]);
    }
    float v1 = 0.f, z1 = 0.f, v2 = 0.f, z2 = 0.f;
    #pragma unroll
    for (int c = 0; c < CPB; c++) {
        int p = base + c;
        float e1 = __expf(g_pm1[p] - mg1);
        float e2 = __expf(g_pm2[p] - mg2);
        v1 += e1 * g_pV1[p * MEMD + j];
        z1 += e1 * g_pz1[p];
        v2 += e2 * g_pV2[p * MEMD + j];
        z2 += e2 * g_pz2[p];
    }
    g_endvec[b * MEMD + j] = v1 / z1;
    g_x1[b * MEMD + j] = v2 / z2;
}

// ---------------- per-turn tail: qe = [s|end_vec]@We^T, GRU step ----------------
__global__ void k_turn2(const float* __restrict__ We,
                        const float* __restrict__ W_ih,
                        const float* __restrict__ W_hh,
                        const float* __restrict__ b_ih,
                        const float* __restrict__ b_hh) {
    extern __shared__ float sm[];
    float* ss  = sm;                    // 32*257
    float* ev  = ss + 32 * 257;
    float* xx  = ev + 32 * 257;
    float* qeo = xx + 32 * 257;         // 32*33
    float* gio = qeo + 32 * 33;         // 96*33
    float* gho = gio + 96 * 33;         // 96*33

    int c = blockIdx.x, t = threadIdx.x;
    for (int i = t; i < BATCH * MEMD; i += 256) {
        int bb = i >> 8, kk = i & 255;
        ss[bb * 257 + kk] = g_s[i];
        ev[bb * 257 + kk] = g_endvec[i];
        xx[bb * 257 + kk] = g_x1[i];
    }
    __syncthreads();

    int w = t >> 5, lane = t & 31;
    const float* srow = &ss[lane * 257];
    const float* erow = &ev[lane * 257];
    const float* xrow = &xx[lane * 257];

    for (int R = w; R < 224; R += 8) {
        float acc;
        if (R < 32) {
            int n = c * 32 + R;
            const float4* Wr0 = (const float4*)(We + (size_t)n * 512);
            const float4* Wr1 = (const float4*)(We + (size_t)n * 512 + 256);
            acc = 0.0f;
            #pragma unroll 8
            for (int k4 = 0; k4 < 64; k4++) {
                float4 wv = __ldg(Wr0 + k4);
                int k = k4 * 4;
                acc += wv.x * srow[k] + wv.y * srow[k + 1] + wv.z * srow[k + 2] + wv.w * srow[k + 3];
            }
            #pragma unroll 8
            for (int k4 = 0; k4 < 64; k4++) {
                float4 wv = __ldg(Wr1 + k4);
                int k = k4 * 4;
                acc += wv.x * erow[k] + wv.y * erow[k + 1] + wv.z * erow[k + 2] + wv.w * erow[k + 3];
            }
            qeo[R * 33 + lane] = acc;
        } else if (R < 128) {
            int idx = R - 32;
            int g = (idx >> 5) * 256 + c * 32 + (idx & 31);
            const float4* Wr = (const float4*)(W_ih + (size_t)g * 256);
            acc = __ldg(b_ih + g);
            #pragma unroll 8
            for (int k4 = 0; k4 < 64; k4++) {
                float4 wv = __ldg(Wr + k4);
                int k = k4 * 4;
                acc += wv.x * xrow[k] + wv.y * xrow[k + 1] + wv.z * xrow[k + 2] + wv.w * xrow[k + 3];
            }
            gio[idx * 33 + lane] = acc;
        } else {
            int idx = R - 128;
            int g = (idx >> 5) * 256 + c * 32 + (idx & 31);
            const float4* Wr = (const float4*)(W_hh + (size_t)g * 256);
            acc = __ldg(b_hh + g);
            #pragma unroll 8
            for (int k4 = 0; k4 < 64; k4++) {
                float4 wv = __ldg(Wr + k4);
                int k = k4 * 4;
                acc += wv.x * srow[k] + wv.y * srow[k + 1] + wv.z * srow[k + 2] + wv.w * srow[k + 3];
            }
            gho[idx * 33 + lane] = acc;
        }
    }
    __syncthreads();

    for (int p = t; p < 1024; p += 256) {
        int bb = p >> 5, jl = p & 31;
        float gir = gio[jl * 33 + bb], giz = gio[(32 + jl) * 33 + bb], gin = gio[(64 + jl) * 33 + bb];
        float ghr = gho[jl * 33 + bb], ghz = gho[(32 + jl) * 33 + bb], ghn = gho[(64 + jl) * 33 + bb];
        float r = 1.0f / (1.0f + __expf(-(gir + ghr)));
        float z = 1.0f / (1.0f + __expf(-(giz + ghz)));
        float n = tanhf(gin + r * ghn);
        int col = c * 32 + jl;
        float sold = ss[bb * 257 + col];
        g_s[bb * MEMD + col] = (1.0f - z) * n + z * sold;
        g_qe[bb * MEMD + col] = qeo[jl * 33 + bb];
    }
}

// ---------------- finalize ----------------
__global__ void k_final(float* __restrict__ out, int n) {
    int i = blockIdx.x * 256 + threadIdx.x;
    if (i < n) out[i] = logf(out[i] * (1.0f / NTURN));
}

// ---------------- launch ----------------
extern "C" void kernel_launch(void* const* d_in, const int* in_sizes, int n_in,
                              void* d_out, int out_size) {
    (void)in_sizes; (void)n_in;
    const float* M    = (const float*)d_in[0];
    const float* s0   = (const float*)d_in[1];
    const float* Wb   = (const float*)d_in[2];
    const float* We   = (const float*)d_in[3];
    const float* Wa   = (const float*)d_in[4];
    const float* W_ih = (const float*)d_in[5];
    const float* W_hh = (const float*)d_in[6];
    const float* b_ih = (const float*)d_in[7];
    const float* b_hh = (const float*)d_in[8];
    float* out = (float*)d_out;

    const int T2_SMEM = (3 * 32 * 257 + 32 * 33 + 2 * 96 * 33) * 4;
    cudaFuncSetAttribute(k_big,   cudaFuncAttributeMaxDynamicSharedMemorySize, BIG_SMEM);
    cudaFuncSetAttribute(k_turn2, cudaFuncAttributeMaxDynamicSharedMemorySize, T2_SMEM);

    int gblocks = (out_size + 255) / 256;
    if (gblocks < 32) gblocks = 32;
    k_init<<<gblocks, 256>>>(out, s0, out_size);
    k_vm2<<<dim3(4, 2), 256>>>(s0, Wb, Wa);

    for (int tn = 0; tn < NTURN; tn++) {
        k_big<<<G_CTAS, 256, BIG_SMEM>>>(M, 1, tn > 0 ? 1 : 0);
        k_softmax_acc<<<dim3(BATCH, 2), 256>>>(out, 1, tn > 0 ? 1 : 0);
        k_reduce<<<BATCH, 256>>>();
        k_turn2<<<8, 256, T2_SMEM>>>(We, W_ih, W_hh, b_ih, b_hh);
        k_vm2<<<dim3(4, 2), 256>>>(nullptr, Wb, Wa);
    }
    k_big<<<G_CTAS, 256, BIG_SMEM>>>(M, 0, 1);
    k_softmax_acc<<<dim3(BATCH, 2), 256>>>(out, 0, 1);
    k_final<<<(out_size + 255) / 256, 256>>>(out, out_size);
}